// round 2
// baseline (speedup 1.0000x reference)
#include <cuda_runtime.h>
#include <cstdint>

// Problem constants
#define BATCH 2048
#define TT    100
#define UD    512
#define G4    2048      // 4*UD
#define NCLS  10

// Tile constants
#define BM 128
#define BK 16
#define NJOBS 768       // 3 layers * 16 mtiles * 16 utiles

// smem: 3-stage pipeline. Per stage: A = 128*20*4 = 10240 B, B = 16*136*4 = 8704 B
#define STAGE_BYTES 18944
#define SMEM_DYN    (3 * STAGE_BYTES)   // 56832; z-buffer (64*130*4=33280) overlaps stages 0-1

// ---------------- scratch (device globals; no allocation) ----------------
__device__ float g_h[3][2][BATCH * UD];   // [layer][t&1][b*UD+u]
__device__ float g_c[3][BATCH * UD];
__device__ float g_Ut[3][UD * G4];        // tf32-rounded U matrices
__device__ float g_Wt[2][UD * G4];        // tf32-rounded W for layers 1,2
__device__ int   g_mask4;                 // 1 if mask elements are 4 bytes
__device__ unsigned g_barcnt;             // monotonic arrival counter
__device__ unsigned g_sense;              // epoch release flag

__device__ __forceinline__ float to_tf32(float v) {
    uint32_t r;
    asm("cvt.rna.tf32.f32 %0, %1;" : "=r"(r) : "f"(v));
    return __uint_as_float(r);
}

__device__ __forceinline__ float sigf(float x) {
    return 1.0f / (1.0f + expf(-x));
}

#define CP16(dst, src) \
    asm volatile("cp.async.cg.shared.global [%0], [%1], 16;\n" :: "r"(dst), "l"(src))

#define MMA_TF32(d, a, b) \
    asm volatile("mma.sync.aligned.m16n8k8.row.col.f32.tf32.tf32.f32 " \
        "{%0,%1,%2,%3},{%4,%5,%6,%7},{%8,%9},{%0,%1,%2,%3};\n" \
        : "+f"(d[0]), "+f"(d[1]), "+f"(d[2]), "+f"(d[3]) \
        : "r"(a[0]), "r"(a[1]), "r"(a[2]), "r"(a[3]), "r"(b[0]), "r"(b[1]))

// ---------------- mask dtype detection ----------------
__global__ void k_detect(const unsigned char* __restrict__ mask) {
    __shared__ int found;
    if (threadIdx.x == 0) found = 0;
    __syncthreads();
    for (int i = threadIdx.x * 4 + 1; i < 4096; i += blockDim.x * 4)
        if (mask[i]) found = 1;
    __syncthreads();
    if (threadIdx.x == 0) g_mask4 = found ? 0 : 1;
}

// ---------------- zero states + barrier vars ----------------
__global__ void k_zero() {
    if (blockIdx.x == 0 && threadIdx.x == 0) { g_barcnt = 0u; g_sense = 0u; }
    const float4 z4 = make_float4(0.f, 0.f, 0.f, 0.f);
    size_t nh = (size_t)3 * 2 * BATCH * UD / 4;
    float4* ph = (float4*)&g_h[0][0][0];
    for (size_t i = (size_t)blockIdx.x * blockDim.x + threadIdx.x; i < nh;
         i += (size_t)gridDim.x * blockDim.x)
        ph[i] = z4;
    size_t nc = (size_t)3 * BATCH * UD / 4;
    float4* pc = (float4*)&g_c[0][0];
    for (size_t i = (size_t)blockIdx.x * blockDim.x + threadIdx.x; i < nc;
         i += (size_t)gridDim.x * blockDim.x)
        pc[i] = z4;
}

// ---------------- round weights to tf32 once per launch ----------------
__global__ void k_round(const float* __restrict__ U0, const float* __restrict__ U1,
                        const float* __restrict__ U2, const float* __restrict__ W1,
                        const float* __restrict__ W2) {
    const int N1 = UD * G4;  // 1048576
    size_t total = (size_t)5 * N1;
    for (size_t i = (size_t)blockIdx.x * blockDim.x + threadIdx.x; i < total;
         i += (size_t)gridDim.x * blockDim.x) {
        int j = (int)(i >> 20);
        int lo = (int)(i & (N1 - 1));
        const float* src;
        float* dst;
        switch (j) {
            case 0: src = U0; dst = g_Ut[0]; break;
            case 1: src = U1; dst = g_Ut[1]; break;
            case 2: src = U2; dst = g_Ut[2]; break;
            case 3: src = W1; dst = g_Wt[0]; break;
            default: src = W2; dst = g_Wt[1]; break;
        }
        dst[lo] = to_tf32(src[lo]);
    }
}

// ---------------- persistent LSTM: all 102 wavefront steps in one kernel ----------------
__global__ __launch_bounds__(256, 2) void lstm_persist(
    const float* __restrict__ x,      // (B, T)
    const void* __restrict__ mask,    // (B, T), 1B or 4B elements
    const float* __restrict__ W0row,  // (2048) layer-0 input weights (in_dim=1)
    const float* __restrict__ b0,
    const float* __restrict__ b1,
    const float* __restrict__ b2,
    int nb)
{
    extern __shared__ __align__(16) char smembuf[];

    const int tid = threadIdx.x;
    const int lane = tid & 31, wid = tid >> 5;
    const int g  = lane >> 2, tg = lane & 3;
    const int wm = wid & 1, wn = wid >> 1;
    const int moff = wm * 64, noff = wn * 32;
    const int mask4 = g_mask4;

    for (int s = 0; s < TT + 2; s++) {
        for (int j = blockIdx.x; j < NJOBS; j += nb) {
            const int layer = j >> 8;
            const int rem = j & 255;
            const int t = s - layer;
            if (t < 0 || t >= TT) continue;

            const int m0 = (rem & 15) * BM;
            const int u0 = (rem >> 4) * 32;

            const float* hprev = g_h[layer][(t + 1) & 1];
            float*       hout  = g_h[layer][t & 1];
            float*       cbuf  = g_c[layer];
            const float* in0   = (layer == 0) ? (const float*)nullptr : g_h[layer - 1][t & 1];
            const float* Wsrc  = (layer == 0) ? (const float*)nullptr : g_Wt[layer - 1];
            const float* Usrc  = g_Ut[layer];
            const float* bias  = (layer == 0) ? b0 : ((layer == 1) ? b1 : b2);
            const int KT = (layer == 0) ? 32 : 64;

            auto issue = [&](int kt) {
                const float* As; const float* Bs; int kk;
                if (layer > 0 && kt < 32) { As = in0;   Bs = Wsrc; kk = kt << 4; }
                else                      { As = hprev; Bs = Usrc; kk = (kt - ((layer > 0) ? 32 : 0)) << 4; }
                const int st = kt % 3;
                uint32_t aB = (uint32_t)__cvta_generic_to_shared(smembuf + st * STAGE_BYTES);
                uint32_t bB = aB + 10240;
                #pragma unroll
                for (int it = 0; it < 2; it++) {
                    int i = tid + it * 256;
                    int m = i >> 2, k4 = i & 3;
                    const float* src = As + (size_t)(m0 + m) * UD + kk + k4 * 4;
                    CP16(aB + (uint32_t)(m * 20 + k4 * 4) * 4, src);
                }
                #pragma unroll
                for (int it = 0; it < 2; it++) {
                    int i = tid + it * 256;
                    int k = i >> 5, r = i & 31;
                    int band = r >> 3, q = r & 7;
                    const float* src = Bs + (size_t)(kk + k) * G4 + band * UD + u0 + q * 4;
                    CP16(bB + (uint32_t)(k * 136 + band * 32 + q * 4) * 4, src);
                }
                asm volatile("cp.async.commit_group;\n" ::);
            };

            float acc[4][4][4];
            #pragma unroll
            for (int i = 0; i < 4; i++)
                #pragma unroll
                for (int jj = 0; jj < 4; jj++)
                    #pragma unroll
                    for (int q = 0; q < 4; q++) acc[i][jj][q] = 0.f;

            issue(0);
            issue(1);

            for (int kt = 0; kt < KT; kt++) {
                if (kt < KT - 1) { asm volatile("cp.async.wait_group 1;\n" ::); }
                else             { asm volatile("cp.async.wait_group 0;\n" ::); }
                __syncthreads();
                if (kt + 2 < KT) issue(kt + 2);

                const int st = kt % 3;
                const uint32_t* Ab = (const uint32_t*)(smembuf + st * STAGE_BYTES);
                const uint32_t* Bb = (const uint32_t*)(smembuf + st * STAGE_BYTES + 10240);

                #pragma unroll
                for (int ks = 0; ks < 2; ks++) {
                    uint32_t a[4][4], b[4][2];
                    #pragma unroll
                    for (int mt = 0; mt < 4; mt++) {
                        int r0 = moff + mt * 16 + g;
                        a[mt][0] = Ab[r0 * 20 + ks * 8 + tg];
                        a[mt][1] = Ab[(r0 + 8) * 20 + ks * 8 + tg];
                        a[mt][2] = Ab[r0 * 20 + ks * 8 + tg + 4];
                        a[mt][3] = Ab[(r0 + 8) * 20 + ks * 8 + tg + 4];
                    }
                    #pragma unroll
                    for (int nt = 0; nt < 4; nt++) {
                        b[nt][0] = Bb[(ks * 8 + tg) * 136 + noff + nt * 8 + g];
                        b[nt][1] = Bb[(ks * 8 + tg + 4) * 136 + noff + nt * 8 + g];
                    }
                    #pragma unroll
                    for (int mt = 0; mt < 4; mt++)
                        #pragma unroll
                        for (int nt = 0; nt < 4; nt++)
                            MMA_TF32(acc[mt][nt], a[mt], b[nt]);
                }
            }

            // --- fused epilogue: z -> gates -> (h, c), mask applied ---
            const int uu = tid & 31;
            const int u  = u0 + uu;
            const float bi = bias[u], bf = bias[UD + u];
            const float bg = bias[2 * UD + u], bo = bias[3 * UD + u];
            float w0i = 0.f, w0f = 0.f, w0g = 0.f, w0o = 0.f;
            if (layer == 0) {
                w0i = W0row[u]; w0f = W0row[UD + u];
                w0g = W0row[2 * UD + u]; w0o = W0row[3 * UD + u];
            }
            float* zsm = (float*)smembuf;   // 64 x 130 floats

            for (int half = 0; half < 2; half++) {
                __syncthreads();
                if (wm == half) {
                    #pragma unroll
                    for (int mt = 0; mt < 4; mt++) {
                        #pragma unroll
                        for (int nt = 0; nt < 4; nt++) {
                            int rl = mt * 16 + g;
                            int cb = noff + nt * 8 + 2 * tg;
                            zsm[rl * 130 + cb]           = acc[mt][nt][0];
                            zsm[rl * 130 + cb + 1]       = acc[mt][nt][1];
                            zsm[(rl + 8) * 130 + cb]     = acc[mt][nt][2];
                            zsm[(rl + 8) * 130 + cb + 1] = acc[mt][nt][3];
                        }
                    }
                }
                __syncthreads();

                #pragma unroll
                for (int r = 0; r < 8; r++) {
                    int ml = wid + r * 8;
                    int brow = m0 + half * 64 + ml;
                    float zi = zsm[ml * 130 + uu]      + bi;
                    float zf = zsm[ml * 130 + 32 + uu] + bf;
                    float zg = zsm[ml * 130 + 64 + uu] + bg;
                    float zo = zsm[ml * 130 + 96 + uu] + bo;
                    if (layer == 0) {
                        float xv = x[(size_t)brow * TT + t];
                        zi += xv * w0i; zf += xv * w0f; zg += xv * w0g; zo += xv * w0o;
                    }
                    float ii = sigf(zi);
                    float ff = sigf(zf);
                    float gg = tanhf(zg);
                    float oo = sigf(zo);

                    size_t idx = (size_t)brow * UD + u;
                    float co = cbuf[idx];
                    float cn = ff * co + ii * gg;
                    float hn = oo * tanhf(cn);

                    size_t midx = (size_t)brow * TT + t;
                    bool msk = mask4 ? (((const unsigned int*)mask)[midx] != 0u)
                                     : (((const unsigned char*)mask)[midx] != 0);
                    if (msk) {
                        cbuf[idx] = cn;
                        hout[idx] = to_tf32(hn);
                    } else {
                        hout[idx] = hprev[idx];
                    }
                }
            }
            __syncthreads();   // protect zsm/stage0 before next job's issue(0)
        }

        // ---- grid-wide barrier (epoch = s, monotonic counter) ----
        if (tid == 0) {
            __threadfence();
            unsigned arrived = atomicAdd(&g_barcnt, 1u) + 1u;
            unsigned target = (unsigned)nb * (unsigned)(s + 1);
            if (arrived == target) {
                atomicExch(&g_sense, (unsigned)(s + 1));
            } else {
                volatile unsigned* vs = &g_sense;
                while (*vs < (unsigned)(s + 1)) { __nanosleep(128); }
            }
            __threadfence();
        }
        __syncthreads();
    }
}

// ---------------- head: logits + softmax ----------------
__global__ void k_head(const float* __restrict__ Wd, const float* __restrict__ bd,
                       float* __restrict__ out) {
    __shared__ float wds[UD * NCLS];
    __shared__ float bds[NCLS];
    int tid = threadIdx.x;
    for (int i = tid; i < UD * NCLS; i += 256) wds[i] = Wd[i];
    if (tid < NCLS) bds[tid] = bd[tid];
    __syncthreads();

    int wid = tid >> 5, lane = tid & 31;
    int b = blockIdx.x * 8 + wid;
    const float* h = g_h[2][(TT - 1) & 1];

    float p[NCLS];
    #pragma unroll
    for (int c = 0; c < NCLS; c++) p[c] = 0.f;
    for (int k = lane; k < UD; k += 32) {
        float hv = h[(size_t)b * UD + k];
        #pragma unroll
        for (int c = 0; c < NCLS; c++) p[c] += hv * wds[k * NCLS + c];
    }
    #pragma unroll
    for (int off = 16; off; off >>= 1)
        #pragma unroll
        for (int c = 0; c < NCLS; c++)
            p[c] += __shfl_down_sync(0xffffffffu, p[c], off);

    if (lane == 0) {
        float l[NCLS], mx = -1e30f;
        #pragma unroll
        for (int c = 0; c < NCLS; c++) { l[c] = p[c] + bds[c]; mx = fmaxf(mx, l[c]); }
        float ssum = 0.f;
        #pragma unroll
        for (int c = 0; c < NCLS; c++) { l[c] = expf(l[c] - mx); ssum += l[c]; }
        float inv = 1.0f / ssum;
        #pragma unroll
        for (int c = 0; c < NCLS; c++) out[(size_t)b * NCLS + c] = l[c] * inv;
    }
}

// ---------------- launch ----------------
extern "C" void kernel_launch(void* const* d_in, const int* in_sizes, int n_in,
                              void* d_out, int out_size) {
    const float* x    = (const float*)d_in[0];
    const void*  mask = d_in[1];
    const float* W0   = (const float*)d_in[2];
    const float* U0   = (const float*)d_in[3];
    const float* b0   = (const float*)d_in[4];
    const float* W1   = (const float*)d_in[5];
    const float* U1   = (const float*)d_in[6];
    const float* b1   = (const float*)d_in[7];
    const float* W2   = (const float*)d_in[8];
    const float* U2   = (const float*)d_in[9];
    const float* b2   = (const float*)d_in[10];
    const float* Wd   = (const float*)d_in[11];
    const float* bd   = (const float*)d_in[12];
    float* out = (float*)d_out;

    cudaFuncSetAttribute(lstm_persist, cudaFuncAttributeMaxDynamicSharedMemorySize, SMEM_DYN);

    int dev = 0;
    cudaGetDevice(&dev);
    int nsm = 148;
    cudaDeviceGetAttribute(&nsm, cudaDevAttrMultiProcessorCount, dev);
    int perSM = 0;
    cudaOccupancyMaxActiveBlocksPerMultiprocessor(&perSM, lstm_persist, 256, SMEM_DYN);
    if (perSM < 1) perSM = 1;
    int nb = nsm * perSM;
    if (nb > NJOBS) nb = NJOBS;

    k_detect<<<1, 256>>>((const unsigned char*)mask);
    k_zero<<<2048, 256>>>();
    k_round<<<2560, 256>>>(U0, U1, U2, W1, W2);

    lstm_persist<<<nb, 256, SMEM_DYN>>>(x, mask, W0, b0, b1, b2, nb);

    k_head<<<BATCH / 8, 256>>>(Wd, bd, out);
}

// round 4
// speedup vs baseline: 2.0507x; 2.0507x over previous
#include <cuda_runtime.h>
#include <cuda_fp16.h>
#include <cstdint>

// Problem constants
#define BATCH 2048
#define TT    100
#define UD    512
#define G4    2048      // 4*UD
#define NCLS  10

// Tile constants
#define BM 128
#define BK 16           // k per stage (= one m16n8k16 step)

// smem: 4-stage pipeline; per stage A=128*48B=6144, B=128*48B=6144
#define ROWB   48       // bytes per smem row (16 halfs data + 8 pad; 16B-aligned)
#define ROWU   12       // uint32 stride per row
#define STAGE_BYTES 12288
#define SMEM_DYN (4 * STAGE_BYTES)   // 49152; z-buffer (64*130*4=33280) fits

// ---------------- scratch (device globals; no allocation) ----------------
__device__ __half g_h16[3][2][BATCH * UD];  // [layer][t&1][b*UD+u]
__device__ float  g_c[3][BATCH * UD];
__device__ __half g_U16[3][G4 * UD];        // transposed: [n][k], k contiguous
__device__ __half g_W16[2][G4 * UD];        // transposed W for layers 1,2
__device__ int    g_mask4;

__device__ __forceinline__ float sigf(float x) {
    return 1.0f / (1.0f + expf(-x));
}

#define CP16(dst, src) \
    asm volatile("cp.async.cg.shared.global [%0], [%1], 16;\n" :: "r"(dst), "l"(src))

#define MMA_F16(d, a, b) \
    asm volatile("mma.sync.aligned.m16n8k16.row.col.f32.f16.f16.f32 " \
        "{%0,%1,%2,%3},{%4,%5,%6,%7},{%8,%9},{%0,%1,%2,%3};\n" \
        : "+f"(d[0]), "+f"(d[1]), "+f"(d[2]), "+f"(d[3]) \
        : "r"(a[0]), "r"(a[1]), "r"(a[2]), "r"(a[3]), "r"(b[0]), "r"(b[1]))

// ---------------- mask dtype detection ----------------
__global__ void k_detect(const unsigned char* __restrict__ mask) {
    __shared__ int found;
    if (threadIdx.x == 0) found = 0;
    __syncthreads();
    for (int i = threadIdx.x * 4 + 1; i < 4096; i += blockDim.x * 4)
        if (mask[i]) found = 1;
    __syncthreads();
    if (threadIdx.x == 0) g_mask4 = found ? 0 : 1;
}

// ---------------- zero states ----------------
__global__ void k_zero() {
    const uint4 z4 = make_uint4(0u, 0u, 0u, 0u);
    size_t nh = (size_t)3 * 2 * BATCH * UD * 2 / 16;   // bytes/16
    uint4* ph = (uint4*)&g_h16[0][0][0];
    for (size_t i = (size_t)blockIdx.x * blockDim.x + threadIdx.x; i < nh;
         i += (size_t)gridDim.x * blockDim.x)
        ph[i] = z4;
    size_t nc = (size_t)3 * BATCH * UD * 4 / 16;
    uint4* pc = (uint4*)&g_c[0][0];
    for (size_t i = (size_t)blockIdx.x * blockDim.x + threadIdx.x; i < nc;
         i += (size_t)gridDim.x * blockDim.x)
        pc[i] = z4;
}

// ---------------- transpose + fp16 convert weights (once) ----------------
// src: [UD rows k][G4 cols n] fp32 -> dst: [G4 rows n][UD cols k] fp16
__global__ void k_trans(const float* __restrict__ U0, const float* __restrict__ U1,
                        const float* __restrict__ U2, const float* __restrict__ W1,
                        const float* __restrict__ W2) {
    const float* src;
    __half* dst;
    switch (blockIdx.z) {
        case 0: src = U0; dst = g_U16[0]; break;
        case 1: src = U1; dst = g_U16[1]; break;
        case 2: src = U2; dst = g_U16[2]; break;
        case 3: src = W1; dst = g_W16[0]; break;
        default: src = W2; dst = g_W16[1]; break;
    }
    __shared__ float t[32][33];
    int n0 = blockIdx.x * 32, k0 = blockIdx.y * 32;
    int tx = threadIdx.x, ty = threadIdx.y;
    #pragma unroll
    for (int i = 0; i < 4; i++)
        t[ty + i * 8][tx] = src[(size_t)(k0 + ty + i * 8) * G4 + n0 + tx];
    __syncthreads();
    #pragma unroll
    for (int i = 0; i < 4; i++)
        dst[(size_t)(n0 + ty + i * 8) * UD + k0 + tx] = __float2half(t[tx][ty + i * 8]);
}

// ---------------- fused LSTM step (3 layers wavefront-pipelined) ----------------
__global__ __launch_bounds__(256, 2) void lstm_step(
    const float* __restrict__ x,      // (B, T)
    const void* __restrict__ mask,    // (B, T), 1B or 4B elements
    const float* __restrict__ W0row,  // (2048) layer-0 input weights (in_dim=1)
    const float* __restrict__ b0,
    const float* __restrict__ b1,
    const float* __restrict__ b2,
    int s)
{
    const int layer = blockIdx.z;
    const int t = s - layer;
    if (t < 0 || t >= TT) return;

    const int m0 = blockIdx.x * BM;
    const int u0 = blockIdx.y * 32;
    const int tid = threadIdx.x;

    const __half* hprev = g_h16[layer][(t + 1) & 1];
    __half*       hout  = g_h16[layer][t & 1];
    float*        cbuf  = g_c[layer];
    const __half* in0   = (layer == 0) ? (const __half*)nullptr : g_h16[layer - 1][t & 1];
    const __half* Wsrc  = (layer == 0) ? (const __half*)nullptr : g_W16[layer - 1];
    const __half* Usrc  = g_U16[layer];
    const float*  bias  = (layer == 0) ? b0 : ((layer == 1) ? b1 : b2);

    extern __shared__ __align__(16) char smembuf[];
    const uint32_t smemB = (uint32_t)__cvta_generic_to_shared(smembuf);

    const int KT = (layer == 0) ? 32 : 64;

    // --- cp.async tile issue: one 16B chunk per thread per tile ---
    auto issue = [&](int kt) {
        const __half* As; const __half* Bs; int kk;
        if (layer > 0 && kt < 32) { As = in0;   Bs = Wsrc; kk = kt << 4; }
        else                      { As = hprev; Bs = Usrc; kk = (kt - ((layer > 0) ? 32 : 0)) << 4; }
        const int st = kt & 3;
        uint32_t aB = smemB + st * STAGE_BYTES;
        uint32_t bB = aB + 6144;
        {
            int m = tid >> 1, c = tid & 1;
            const __half* src = As + (size_t)(m0 + m) * UD + kk + c * 8;
            CP16(aB + (uint32_t)(m * ROWB + c * 16), src);
        }
        {
            int nl = tid >> 1, c = tid & 1;
            int band = nl >> 5, q = nl & 31;
            int n = band * UD + u0 + q;
            const __half* src = Bs + (size_t)n * UD + kk + c * 8;
            CP16(bB + (uint32_t)(nl * ROWB + c * 16), src);
        }
        asm volatile("cp.async.commit_group;\n" ::);
    };

    // --- warp / fragment decomposition ---
    const int lane = tid & 31, wid = tid >> 5;
    const int g  = lane >> 2, tg = lane & 3;
    const int wm = wid & 1, wn = wid >> 1;
    const int moff = wm * 64, noff = wn * 32;

    float acc[4][4][4];
    #pragma unroll
    for (int i = 0; i < 4; i++)
        #pragma unroll
        for (int j = 0; j < 4; j++)
            #pragma unroll
            for (int q = 0; q < 4; q++) acc[i][j][q] = 0.f;

    issue(0);
    issue(1);
    issue(2);

    for (int kt = 0; kt < KT; kt++) {
        if (kt < KT - 2)      { asm volatile("cp.async.wait_group 2;\n" ::); }
        else if (kt == KT - 2){ asm volatile("cp.async.wait_group 1;\n" ::); }
        else                  { asm volatile("cp.async.wait_group 0;\n" ::); }
        __syncthreads();
        if (kt + 3 < KT) issue(kt + 3);

        const int st = kt & 3;
        const uint32_t* Ab = (const uint32_t*)(smembuf + st * STAGE_BYTES);
        const uint32_t* Bb = Ab + 1536;

        uint32_t a[4][4], b[4][2];
        #pragma unroll
        for (int mt = 0; mt < 4; mt++) {
            int r0 = moff + mt * 16 + g;
            a[mt][0] = Ab[r0 * ROWU + tg];
            a[mt][1] = Ab[(r0 + 8) * ROWU + tg];
            a[mt][2] = Ab[r0 * ROWU + tg + 4];
            a[mt][3] = Ab[(r0 + 8) * ROWU + tg + 4];
        }
        #pragma unroll
        for (int nt = 0; nt < 4; nt++) {
            int nn = noff + nt * 8 + g;
            b[nt][0] = Bb[nn * ROWU + tg];
            b[nt][1] = Bb[nn * ROWU + tg + 4];
        }
        #pragma unroll
        for (int mt = 0; mt < 4; mt++)
            #pragma unroll
            for (int nt = 0; nt < 4; nt++)
                MMA_F16(acc[mt][nt], a[mt], b[nt]);
    }

    // --- fused epilogue: z -> gates -> (h, c), mask applied ---
    const int mask4 = g_mask4;
    const int uu = tid & 31;
    const int u  = u0 + uu;
    const float bi = bias[u], bf = bias[UD + u];
    const float bg = bias[2 * UD + u], bo = bias[3 * UD + u];
    float w0i = 0.f, w0f = 0.f, w0g = 0.f, w0o = 0.f;
    if (layer == 0) {
        w0i = W0row[u]; w0f = W0row[UD + u];
        w0g = W0row[2 * UD + u]; w0o = W0row[3 * UD + u];
    }
    float* zsm = (float*)smembuf;   // 64 x 130 floats

    for (int half = 0; half < 2; half++) {
        __syncthreads();
        if (wm == half) {
            #pragma unroll
            for (int mt = 0; mt < 4; mt++) {
                #pragma unroll
                for (int nt = 0; nt < 4; nt++) {
                    int rl = mt * 16 + g;
                    int cb = noff + nt * 8 + 2 * tg;
                    zsm[rl * 130 + cb]           = acc[mt][nt][0];
                    zsm[rl * 130 + cb + 1]       = acc[mt][nt][1];
                    zsm[(rl + 8) * 130 + cb]     = acc[mt][nt][2];
                    zsm[(rl + 8) * 130 + cb + 1] = acc[mt][nt][3];
                }
            }
        }
        __syncthreads();

        #pragma unroll
        for (int r = 0; r < 8; r++) {
            int ml = wid + r * 8;
            int brow = m0 + half * 64 + ml;
            float zi = zsm[ml * 130 + uu]      + bi;
            float zf = zsm[ml * 130 + 32 + uu] + bf;
            float zg = zsm[ml * 130 + 64 + uu] + bg;
            float zo = zsm[ml * 130 + 96 + uu] + bo;
            if (layer == 0) {
                float xv = x[(size_t)brow * TT + t];
                zi += xv * w0i; zf += xv * w0f; zg += xv * w0g; zo += xv * w0o;
            }
            float ii = sigf(zi);
            float ff = sigf(zf);
            float gg = tanhf(zg);
            float oo = sigf(zo);

            size_t idx = (size_t)brow * UD + u;
            float co = cbuf[idx];
            float cn = ff * co + ii * gg;
            float hn = oo * tanhf(cn);

            size_t midx = (size_t)brow * TT + t;
            bool msk = mask4 ? (((const unsigned int*)mask)[midx] != 0u)
                             : (((const unsigned char*)mask)[midx] != 0);
            if (msk) {
                cbuf[idx] = cn;
                hout[idx] = __float2half(hn);
            } else {
                hout[idx] = hprev[idx];
            }
        }
    }
}

// ---------------- head: logits + softmax ----------------
__global__ void k_head(const float* __restrict__ Wd, const float* __restrict__ bd,
                       float* __restrict__ out) {
    __shared__ float wds[UD * NCLS];
    __shared__ float bds[NCLS];
    int tid = threadIdx.x;
    for (int i = tid; i < UD * NCLS; i += 256) wds[i] = Wd[i];
    if (tid < NCLS) bds[tid] = bd[tid];
    __syncthreads();

    int wid = tid >> 5, lane = tid & 31;
    int b = blockIdx.x * 8 + wid;
    const __half* h = g_h16[2][(TT - 1) & 1];

    float p[NCLS];
    #pragma unroll
    for (int c = 0; c < NCLS; c++) p[c] = 0.f;
    for (int k = lane; k < UD; k += 32) {
        float hv = __half2float(h[(size_t)b * UD + k]);
        #pragma unroll
        for (int c = 0; c < NCLS; c++) p[c] += hv * wds[k * NCLS + c];
    }
    #pragma unroll
    for (int off = 16; off; off >>= 1)
        #pragma unroll
        for (int c = 0; c < NCLS; c++)
            p[c] += __shfl_down_sync(0xffffffffu, p[c], off);

    if (lane == 0) {
        float l[NCLS], mx = -1e30f;
        #pragma unroll
        for (int c = 0; c < NCLS; c++) { l[c] = p[c] + bds[c]; mx = fmaxf(mx, l[c]); }
        float ssum = 0.f;
        #pragma unroll
        for (int c = 0; c < NCLS; c++) { l[c] = expf(l[c] - mx); ssum += l[c]; }
        float inv = 1.0f / ssum;
        #pragma unroll
        for (int c = 0; c < NCLS; c++) out[(size_t)b * NCLS + c] = l[c] * inv;
    }
}

// ---------------- launch ----------------
extern "C" void kernel_launch(void* const* d_in, const int* in_sizes, int n_in,
                              void* d_out, int out_size) {
    const float* x    = (const float*)d_in[0];
    const void*  mask = d_in[1];
    const float* W0   = (const float*)d_in[2];
    const float* U0   = (const float*)d_in[3];
    const float* b0   = (const float*)d_in[4];
    const float* W1   = (const float*)d_in[5];
    const float* U1   = (const float*)d_in[6];
    const float* b1   = (const float*)d_in[7];
    const float* W2   = (const float*)d_in[8];
    const float* U2   = (const float*)d_in[9];
    const float* b2   = (const float*)d_in[10];
    const float* Wd   = (const float*)d_in[11];
    const float* bd   = (const float*)d_in[12];
    float* out = (float*)d_out;

    cudaFuncSetAttribute(lstm_step, cudaFuncAttributeMaxDynamicSharedMemorySize, SMEM_DYN);

    k_detect<<<1, 256>>>((const unsigned char*)mask);
    k_zero<<<1024, 256>>>();
    k_trans<<<dim3(G4 / 32, UD / 32, 5), dim3(32, 8)>>>(U0, U1, U2, W1, W2);

    dim3 grid(BATCH / BM, UD / 32, 3);
    for (int s = 0; s < TT + 2; s++) {
        lstm_step<<<grid, 256, SMEM_DYN>>>(x, mask, W0, b0, b1, b2, s);
    }
    k_head<<<BATCH / 8, 256>>>(Wd, bd, out);
}

// round 5
// speedup vs baseline: 2.0634x; 1.0062x over previous
#include <cuda_runtime.h>
#include <cuda_fp16.h>
#include <cstdint>

// Problem constants
#define BATCH 2048
#define TT    100
#define UD    512
#define G4    2048      // 4*UD
#define NCLS  10

// Tile constants
#define BM 128
#define NJOBS 768       // 3 layers * 16 mtiles * 16 utiles

// smem: 4-stage pipeline; per stage A=128*48B=6144, B=128*48B=6144
#define ROWB   48
#define ROWU   12
#define STAGE_BYTES 12288
#define SMEM_DYN (4 * STAGE_BYTES)   // 49152; z-buffer (64*130*4=33280) fits

// ---------------- scratch (device globals; no allocation) ----------------
__device__ __half g_h16[3][2][BATCH * UD];  // [layer][t&1][b*UD+u]
__device__ float  g_c[3][BATCH * UD];
__device__ __half g_U16[3][G4 * UD];        // transposed: [n][k], k contiguous
__device__ __half g_W16[2][G4 * UD];        // transposed W for layers 1,2
__device__ int    g_mask4;
__device__ unsigned g_ctr[TT + 4];          // per-step job counters
__device__ unsigned g_barcnt;               // monotonic arrival counter
__device__ unsigned g_go;                   // epoch release flag

__device__ __forceinline__ float sigf(float x) {
    return 1.0f / (1.0f + expf(-x));
}

#define CP16(dst, src) \
    asm volatile("cp.async.cg.shared.global [%0], [%1], 16;\n" :: "r"(dst), "l"(src))

#define MMA_F16(d, a, b) \
    asm volatile("mma.sync.aligned.m16n8k16.row.col.f32.f16.f16.f32 " \
        "{%0,%1,%2,%3},{%4,%5,%6,%7},{%8,%9},{%0,%1,%2,%3};\n" \
        : "+f"(d[0]), "+f"(d[1]), "+f"(d[2]), "+f"(d[3]) \
        : "r"(a[0]), "r"(a[1]), "r"(a[2]), "r"(a[3]), "r"(b[0]), "r"(b[1]))

// ---------------- mask dtype detection ----------------
__global__ void k_detect(const unsigned char* __restrict__ mask) {
    __shared__ int found;
    if (threadIdx.x == 0) found = 0;
    __syncthreads();
    for (int i = threadIdx.x * 4 + 1; i < 4096; i += blockDim.x * 4)
        if (mask[i]) found = 1;
    __syncthreads();
    if (threadIdx.x == 0) g_mask4 = found ? 0 : 1;
}

// ---------------- zero states + sync vars ----------------
__global__ void k_zero() {
    if (blockIdx.x == 0) {
        if (threadIdx.x == 0) { g_barcnt = 0u; g_go = 0u; }
        if (threadIdx.x < TT + 4) g_ctr[threadIdx.x] = 0u;
    }
    const uint4 z4 = make_uint4(0u, 0u, 0u, 0u);
    size_t nh = (size_t)3 * 2 * BATCH * UD * 2 / 16;   // bytes/16
    uint4* ph = (uint4*)&g_h16[0][0][0];
    for (size_t i = (size_t)blockIdx.x * blockDim.x + threadIdx.x; i < nh;
         i += (size_t)gridDim.x * blockDim.x)
        ph[i] = z4;
    size_t nc = (size_t)3 * BATCH * UD * 4 / 16;
    uint4* pc = (uint4*)&g_c[0][0];
    for (size_t i = (size_t)blockIdx.x * blockDim.x + threadIdx.x; i < nc;
         i += (size_t)gridDim.x * blockDim.x)
        pc[i] = z4;
}

// ---------------- transpose + fp16 convert weights (once) ----------------
__global__ void k_trans(const float* __restrict__ U0, const float* __restrict__ U1,
                        const float* __restrict__ U2, const float* __restrict__ W1,
                        const float* __restrict__ W2) {
    const float* src;
    __half* dst;
    switch (blockIdx.z) {
        case 0: src = U0; dst = g_U16[0]; break;
        case 1: src = U1; dst = g_U16[1]; break;
        case 2: src = U2; dst = g_U16[2]; break;
        case 3: src = W1; dst = g_W16[0]; break;
        default: src = W2; dst = g_W16[1]; break;
    }
    __shared__ float t[32][33];
    int n0 = blockIdx.x * 32, k0 = blockIdx.y * 32;
    int tx = threadIdx.x, ty = threadIdx.y;
    #pragma unroll
    for (int i = 0; i < 4; i++)
        t[ty + i * 8][tx] = src[(size_t)(k0 + ty + i * 8) * G4 + n0 + tx];
    __syncthreads();
    #pragma unroll
    for (int i = 0; i < 4; i++)
        dst[(size_t)(n0 + ty + i * 8) * UD + k0 + tx] = __float2half(t[tx][ty + i * 8]);
}

// ---------------- persistent LSTM: work-stealing + grid barrier ----------------
__global__ __launch_bounds__(256, 2) void lstm_persist(
    const float* __restrict__ x,      // (B, T)
    const void* __restrict__ mask,    // (B, T), 1B or 4B elements
    const float* __restrict__ W0row,  // (2048) layer-0 input weights
    const float* __restrict__ b0,
    const float* __restrict__ b1,
    const float* __restrict__ b2,
    int nb)
{
    extern __shared__ __align__(16) char smembuf[];
    __shared__ int smem_job;
    const uint32_t smemB = (uint32_t)__cvta_generic_to_shared(smembuf);

    const int tid = threadIdx.x;
    const int lane = tid & 31, wid = tid >> 5;
    const int g  = lane >> 2, tg = lane & 3;
    const int wm = wid & 1, wn = wid >> 1;
    const int moff = wm * 64, noff = wn * 32;
    const int mask4 = g_mask4;

    for (int s = 0; s < TT + 2; s++) {
        // ---- work-stealing loop over this step's jobs ----
        while (true) {
            __syncthreads();   // all threads done with previous smem_job / smem
            if (tid == 0) smem_job = (int)atomicAdd(&g_ctr[s], 1u);
            __syncthreads();
            const int j = smem_job;
            if (j >= NJOBS) break;

            const int layer = j >> 8;
            const int rem = j & 255;
            const int t = s - layer;
            if (t < 0 || t >= TT) continue;

            const int m0 = (rem & 15) * BM;
            const int u0 = (rem >> 4) * 32;

            const __half* hprev = g_h16[layer][(t + 1) & 1];
            __half*       hout  = g_h16[layer][t & 1];
            float*        cbuf  = g_c[layer];
            const __half* in0   = (layer == 0) ? (const __half*)nullptr : g_h16[layer - 1][t & 1];
            const __half* Wsrc  = (layer == 0) ? (const __half*)nullptr : g_W16[layer - 1];
            const __half* Usrc  = g_U16[layer];
            const float*  bias  = (layer == 0) ? b0 : ((layer == 1) ? b1 : b2);
            const int KT = (layer == 0) ? 32 : 64;

            auto issue = [&](int kt) {
                const __half* As; const __half* Bs; int kk;
                if (layer > 0 && kt < 32) { As = in0;   Bs = Wsrc; kk = kt << 4; }
                else                      { As = hprev; Bs = Usrc; kk = (kt - ((layer > 0) ? 32 : 0)) << 4; }
                const int st = kt & 3;
                uint32_t aB = smemB + st * STAGE_BYTES;
                uint32_t bB = aB + 6144;
                {
                    int m = tid >> 1, c = tid & 1;
                    const __half* src = As + (size_t)(m0 + m) * UD + kk + c * 8;
                    CP16(aB + (uint32_t)(m * ROWB + c * 16), src);
                }
                {
                    int nl = tid >> 1, c = tid & 1;
                    int band = nl >> 5, q = nl & 31;
                    int n = band * UD + u0 + q;
                    const __half* src = Bs + (size_t)n * UD + kk + c * 8;
                    CP16(bB + (uint32_t)(nl * ROWB + c * 16), src);
                }
                asm volatile("cp.async.commit_group;\n" ::);
            };

            float acc[4][4][4];
            #pragma unroll
            for (int i = 0; i < 4; i++)
                #pragma unroll
                for (int jj = 0; jj < 4; jj++)
                    #pragma unroll
                    for (int q = 0; q < 4; q++) acc[i][jj][q] = 0.f;

            issue(0);
            issue(1);
            issue(2);

            for (int kt = 0; kt < KT; kt++) {
                if (kt < KT - 2)      { asm volatile("cp.async.wait_group 2;\n" ::); }
                else if (kt == KT - 2){ asm volatile("cp.async.wait_group 1;\n" ::); }
                else                  { asm volatile("cp.async.wait_group 0;\n" ::); }
                __syncthreads();
                if (kt + 3 < KT) issue(kt + 3);

                const int st = kt & 3;
                const uint32_t* Ab = (const uint32_t*)(smembuf + st * STAGE_BYTES);
                const uint32_t* Bb = Ab + 1536;

                uint32_t a[4][4], b[4][2];
                #pragma unroll
                for (int mt = 0; mt < 4; mt++) {
                    int r0 = moff + mt * 16 + g;
                    a[mt][0] = Ab[r0 * ROWU + tg];
                    a[mt][1] = Ab[(r0 + 8) * ROWU + tg];
                    a[mt][2] = Ab[r0 * ROWU + tg + 4];
                    a[mt][3] = Ab[(r0 + 8) * ROWU + tg + 4];
                }
                #pragma unroll
                for (int nt = 0; nt < 4; nt++) {
                    int nn = noff + nt * 8 + g;
                    b[nt][0] = Bb[nn * ROWU + tg];
                    b[nt][1] = Bb[nn * ROWU + tg + 4];
                }
                #pragma unroll
                for (int mt = 0; mt < 4; mt++)
                    #pragma unroll
                    for (int nt = 0; nt < 4; nt++)
                        MMA_F16(acc[mt][nt], a[mt], b[nt]);
            }

            // --- fused epilogue ---
            const int uu = tid & 31;
            const int u  = u0 + uu;
            const float bi = bias[u], bf = bias[UD + u];
            const float bg = bias[2 * UD + u], bo = bias[3 * UD + u];
            float w0i = 0.f, w0f = 0.f, w0g = 0.f, w0o = 0.f;
            if (layer == 0) {
                w0i = W0row[u]; w0f = W0row[UD + u];
                w0g = W0row[2 * UD + u]; w0o = W0row[3 * UD + u];
            }
            float* zsm = (float*)smembuf;   // 64 x 130 floats

            for (int half = 0; half < 2; half++) {
                __syncthreads();
                if (wm == half) {
                    #pragma unroll
                    for (int mt = 0; mt < 4; mt++) {
                        #pragma unroll
                        for (int nt = 0; nt < 4; nt++) {
                            int rl = mt * 16 + g;
                            int cb = noff + nt * 8 + 2 * tg;
                            zsm[rl * 130 + cb]           = acc[mt][nt][0];
                            zsm[rl * 130 + cb + 1]       = acc[mt][nt][1];
                            zsm[(rl + 8) * 130 + cb]     = acc[mt][nt][2];
                            zsm[(rl + 8) * 130 + cb + 1] = acc[mt][nt][3];
                        }
                    }
                }
                __syncthreads();

                #pragma unroll
                for (int r = 0; r < 8; r++) {
                    int ml = wid + r * 8;
                    int brow = m0 + half * 64 + ml;
                    float zi = zsm[ml * 130 + uu]      + bi;
                    float zf = zsm[ml * 130 + 32 + uu] + bf;
                    float zg = zsm[ml * 130 + 64 + uu] + bg;
                    float zo = zsm[ml * 130 + 96 + uu] + bo;
                    if (layer == 0) {
                        float xv = x[(size_t)brow * TT + t];
                        zi += xv * w0i; zf += xv * w0f; zg += xv * w0g; zo += xv * w0o;
                    }
                    float ii = sigf(zi);
                    float ff = sigf(zf);
                    float gg = tanhf(zg);
                    float oo = sigf(zo);

                    size_t idx = (size_t)brow * UD + u;
                    float co = cbuf[idx];
                    float cn = ff * co + ii * gg;
                    float hn = oo * tanhf(cn);

                    size_t midx = (size_t)brow * TT + t;
                    bool msk = mask4 ? (((const unsigned int*)mask)[midx] != 0u)
                                     : (((const unsigned char*)mask)[midx] != 0);
                    if (msk) {
                        cbuf[idx] = cn;
                        hout[idx] = __float2half(hn);
                    } else {
                        hout[idx] = hprev[idx];
                    }
                }
            }
        }

        // ---- grid-wide barrier (epoch s, monotonic counter) ----
        if (tid == 0) {
            __threadfence();
            unsigned arrived = atomicAdd(&g_barcnt, 1u) + 1u;
            unsigned target = (unsigned)nb * (unsigned)(s + 1);
            if (arrived == target) {
                atomicExch(&g_go, (unsigned)(s + 1));
            } else {
                volatile unsigned* vs = &g_go;
                while (*vs < (unsigned)(s + 1)) { __nanosleep(64); }
            }
            __threadfence();
        }
        __syncthreads();
    }
}

// ---------------- head: logits + softmax ----------------
__global__ void k_head(const float* __restrict__ Wd, const float* __restrict__ bd,
                       float* __restrict__ out) {
    __shared__ float wds[UD * NCLS];
    __shared__ float bds[NCLS];
    int tid = threadIdx.x;
    for (int i = tid; i < UD * NCLS; i += 256) wds[i] = Wd[i];
    if (tid < NCLS) bds[tid] = bd[tid];
    __syncthreads();

    int wid = tid >> 5, lane = tid & 31;
    int b = blockIdx.x * 8 + wid;
    const __half* h = g_h16[2][(TT - 1) & 1];

    float p[NCLS];
    #pragma unroll
    for (int c = 0; c < NCLS; c++) p[c] = 0.f;
    for (int k = lane; k < UD; k += 32) {
        float hv = __half2float(h[(size_t)b * UD + k]);
        #pragma unroll
        for (int c = 0; c < NCLS; c++) p[c] += hv * wds[k * NCLS + c];
    }
    #pragma unroll
    for (int off = 16; off; off >>= 1)
        #pragma unroll
        for (int c = 0; c < NCLS; c++)
            p[c] += __shfl_down_sync(0xffffffffu, p[c], off);

    if (lane == 0) {
        float l[NCLS], mx = -1e30f;
        #pragma unroll
        for (int c = 0; c < NCLS; c++) { l[c] = p[c] + bds[c]; mx = fmaxf(mx, l[c]); }
        float ssum = 0.f;
        #pragma unroll
        for (int c = 0; c < NCLS; c++) { l[c] = expf(l[c] - mx); ssum += l[c]; }
        float inv = 1.0f / ssum;
        #pragma unroll
        for (int c = 0; c < NCLS; c++) out[(size_t)b * NCLS + c] = l[c] * inv;
    }
}

// ---------------- launch ----------------
extern "C" void kernel_launch(void* const* d_in, const int* in_sizes, int n_in,
                              void* d_out, int out_size) {
    const float* x    = (const float*)d_in[0];
    const void*  mask = d_in[1];
    const float* W0   = (const float*)d_in[2];
    const float* U0   = (const float*)d_in[3];
    const float* b0   = (const float*)d_in[4];
    const float* W1   = (const float*)d_in[5];
    const float* U1   = (const float*)d_in[6];
    const float* b1   = (const float*)d_in[7];
    const float* W2   = (const float*)d_in[8];
    const float* U2   = (const float*)d_in[9];
    const float* b2   = (const float*)d_in[10];
    const float* Wd   = (const float*)d_in[11];
    const float* bd   = (const float*)d_in[12];
    float* out = (float*)d_out;

    cudaFuncSetAttribute(lstm_persist, cudaFuncAttributeMaxDynamicSharedMemorySize, SMEM_DYN);

    int dev = 0;
    cudaGetDevice(&dev);
    int nsm = 148;
    cudaDeviceGetAttribute(&nsm, cudaDevAttrMultiProcessorCount, dev);
    int perSM = 0;
    cudaOccupancyMaxActiveBlocksPerMultiprocessor(&perSM, lstm_persist, 256, SMEM_DYN);
    if (perSM < 1) perSM = 1;
    int nb = nsm * perSM;
    if (nb > NJOBS) nb = NJOBS;

    k_detect<<<1, 256>>>((const unsigned char*)mask);
    k_zero<<<1024, 256>>>();
    k_trans<<<dim3(G4 / 32, UD / 32, 5), dim3(32, 8)>>>(U0, U1, U2, W1, W2);

    lstm_persist<<<nb, 256, SMEM_DYN>>>(x, mask, W0, b0, b1, b2, nb);

    k_head<<<BATCH / 8, 256>>>(Wd, bd, out);
}

// round 13
// speedup vs baseline: 2.3259x; 1.1272x over previous
#include <cuda_runtime.h>
#include <cuda_fp16.h>
#include <cstdint>

// Problem constants
#define BATCH 2048
#define TT    100
#define UD    512
#define G4    2048      // 4*UD
#define NCLS  10

// Tile constants
#define BM 128
#define NJOBS 768       // 3 layers * 16 mtiles * 16 utiles

// smem: 4-stage pipeline; per stage A=128*80B=10240, B=128*80B=10240
// BK=32 (two m16n8k16 k-steps per stage)
#define ROWB   80       // bytes per smem row (32 halfs data + 8 pad halfs)
#define ROWU   20       // uint32 stride per row
#define STAGE_BYTES 20480
#define SMEM_DYN (4 * STAGE_BYTES)   // 81920; z-buffer (64*130*4=33280) fits

// ---------------- scratch (device globals; no allocation) ----------------
__device__ __half g_h16[3][2][BATCH * UD];  // [layer][t&1][b*UD+u]
__device__ float  g_c[3][BATCH * UD];
__device__ __half g_U16[3][G4 * UD];        // transposed: [n][k], k contiguous
__device__ __half g_W16[2][G4 * UD];        // transposed W for layers 1,2
__device__ int    g_mask4;
__device__ unsigned g_ctr[TT + 4];          // per-step job counters
__device__ unsigned g_barcnt;               // monotonic arrival counter
__device__ unsigned g_go;                   // epoch release flag

__device__ __forceinline__ float sigf(float x) {
    return 1.0f / (1.0f + expf(-x));
}

#define CP16(dst, src) \
    asm volatile("cp.async.cg.shared.global [%0], [%1], 16;\n" :: "r"(dst), "l"(src))

#define MMA_F16(d, a, b) \
    asm volatile("mma.sync.aligned.m16n8k16.row.col.f32.f16.f16.f32 " \
        "{%0,%1,%2,%3},{%4,%5,%6,%7},{%8,%9},{%0,%1,%2,%3};\n" \
        : "+f"(d[0]), "+f"(d[1]), "+f"(d[2]), "+f"(d[3]) \
        : "r"(a[0]), "r"(a[1]), "r"(a[2]), "r"(a[3]), "r"(b[0]), "r"(b[1]))

// ---------------- mask dtype detection ----------------
__global__ void k_detect(const unsigned char* __restrict__ mask) {
    __shared__ int found;
    if (threadIdx.x == 0) found = 0;
    __syncthreads();
    for (int i = threadIdx.x * 4 + 1; i < 4096; i += blockDim.x * 4)
        if (mask[i]) found = 1;
    __syncthreads();
    if (threadIdx.x == 0) g_mask4 = found ? 0 : 1;
}

// ---------------- zero states + sync vars ----------------
__global__ void k_zero() {
    if (blockIdx.x == 0) {
        if (threadIdx.x == 0) { g_barcnt = 0u; g_go = 0u; }
        if (threadIdx.x < TT + 4) g_ctr[threadIdx.x] = 0u;
    }
    const uint4 z4 = make_uint4(0u, 0u, 0u, 0u);
    size_t nh = (size_t)3 * 2 * BATCH * UD * 2 / 16;   // bytes/16
    uint4* ph = (uint4*)&g_h16[0][0][0];
    for (size_t i = (size_t)blockIdx.x * blockDim.x + threadIdx.x; i < nh;
         i += (size_t)gridDim.x * blockDim.x)
        ph[i] = z4;
    size_t nc = (size_t)3 * BATCH * UD * 4 / 16;
    uint4* pc = (uint4*)&g_c[0][0];
    for (size_t i = (size_t)blockIdx.x * blockDim.x + threadIdx.x; i < nc;
         i += (size_t)gridDim.x * blockDim.x)
        pc[i] = z4;
}

// ---------------- transpose + fp16 convert weights (once) ----------------
__global__ void k_trans(const float* __restrict__ U0, const float* __restrict__ U1,
                        const float* __restrict__ U2, const float* __restrict__ W1,
                        const float* __restrict__ W2) {
    const float* src;
    __half* dst;
    switch (blockIdx.z) {
        case 0: src = U0; dst = g_U16[0]; break;
        case 1: src = U1; dst = g_U16[1]; break;
        case 2: src = U2; dst = g_U16[2]; break;
        case 3: src = W1; dst = g_W16[0]; break;
        default: src = W2; dst = g_W16[1]; break;
    }
    __shared__ float t[32][33];
    int n0 = blockIdx.x * 32, k0 = blockIdx.y * 32;
    int tx = threadIdx.x, ty = threadIdx.y;
    #pragma unroll
    for (int i = 0; i < 4; i++)
        t[ty + i * 8][tx] = src[(size_t)(k0 + ty + i * 8) * G4 + n0 + tx];
    __syncthreads();
    #pragma unroll
    for (int i = 0; i < 4; i++)
        dst[(size_t)(n0 + ty + i * 8) * UD + k0 + tx] = __float2half(t[tx][ty + i * 8]);
}

// ---------------- persistent LSTM: work-stealing + grid barrier ----------------
__global__ __launch_bounds__(256, 2) void lstm_persist(
    const float* __restrict__ x,      // (B, T)
    const void* __restrict__ mask,    // (B, T), 1B or 4B elements
    const float* __restrict__ W0row,  // (2048) layer-0 input weights
    const float* __restrict__ b0,
    const float* __restrict__ b1,
    const float* __restrict__ b2,
    int nb)
{
    extern __shared__ __align__(16) char smembuf[];
    __shared__ int smem_job;
    const uint32_t smemB = (uint32_t)__cvta_generic_to_shared(smembuf);

    const int tid = threadIdx.x;
    const int lane = tid & 31, wid = tid >> 5;
    const int g  = lane >> 2, tg = lane & 3;
    const int wm = wid & 1, wn = wid >> 1;
    const int moff = wm * 64, noff = wn * 32;
    const int mask4 = g_mask4;

    for (int s = 0; s < TT + 2; s++) {
        // ---- work-stealing loop over this step's jobs ----
        while (true) {
            __syncthreads();   // all threads done with previous smem_job / smem
            if (tid == 0) smem_job = (int)atomicAdd(&g_ctr[s], 1u);
            __syncthreads();
            const int j = smem_job;
            if (j >= NJOBS) break;

            const int layer = j >> 8;
            const int rem = j & 255;
            const int t = s - layer;
            if (t < 0 || t >= TT) continue;

            const int m0 = (rem & 15) * BM;
            const int u0 = (rem >> 4) * 32;

            const __half* hprev = g_h16[layer][(t + 1) & 1];
            __half*       hout  = g_h16[layer][t & 1];
            float*        cbuf  = g_c[layer];
            const __half* in0   = (layer == 0) ? (const __half*)nullptr : g_h16[layer - 1][t & 1];
            const __half* Wsrc  = (layer == 0) ? (const __half*)nullptr : g_W16[layer - 1];
            const __half* Usrc  = g_U16[layer];
            const float*  bias  = (layer == 0) ? b0 : ((layer == 1) ? b1 : b2);
            const int KT = (layer == 0) ? 16 : 32;   // BK=32 per stage

            auto issue = [&](int kt) {
                const __half* As; const __half* Bs; int kk;
                if (layer > 0 && kt < 16) { As = in0;   Bs = Wsrc; kk = kt << 5; }
                else                      { As = hprev; Bs = Usrc; kk = (kt - ((layer > 0) ? 16 : 0)) << 5; }
                const int st = kt & 3;
                uint32_t aB = smemB + st * STAGE_BYTES;
                uint32_t bB = aB + 10240;
                #pragma unroll
                for (int it = 0; it < 2; it++) {
                    int i = tid + it * 256;
                    int m = i >> 2, c = i & 3;
                    const __half* src = As + (size_t)(m0 + m) * UD + kk + c * 8;
                    CP16(aB + (uint32_t)(m * ROWB + c * 16), src);
                }
                #pragma unroll
                for (int it = 0; it < 2; it++) {
                    int i = tid + it * 256;
                    int nl = i >> 2, c = i & 3;
                    int band = nl >> 5, q = nl & 31;
                    int n = band * UD + u0 + q;
                    const __half* src = Bs + (size_t)n * UD + kk + c * 8;
                    CP16(bB + (uint32_t)(nl * ROWB + c * 16), src);
                }
                asm volatile("cp.async.commit_group;\n" ::);
            };

            float acc[4][4][4];
            #pragma unroll
            for (int i = 0; i < 4; i++)
                #pragma unroll
                for (int jj = 0; jj < 4; jj++)
                    #pragma unroll
                    for (int q = 0; q < 4; q++) acc[i][jj][q] = 0.f;

            issue(0);
            issue(1);
            issue(2);

            for (int kt = 0; kt < KT; kt++) {
                int ahead = KT - 1 - kt;     // stages issued beyond kt
                if (ahead >= 2)      { asm volatile("cp.async.wait_group 2;\n" ::); }
                else if (ahead == 1) { asm volatile("cp.async.wait_group 1;\n" ::); }
                else                 { asm volatile("cp.async.wait_group 0;\n" ::); }
                __syncthreads();
                if (kt + 3 < KT) issue(kt + 3);

                const int st = kt & 3;
                const uint32_t* Ab = (const uint32_t*)(smembuf + st * STAGE_BYTES);
                const uint32_t* Bb = Ab + 2560;   // 10240 bytes

                #pragma unroll
                for (int ks = 0; ks < 2; ks++) {
                    uint32_t a[4][4], b[4][2];
                    #pragma unroll
                    for (int mt = 0; mt < 4; mt++) {
                        int r0 = moff + mt * 16 + g;
                        a[mt][0] = Ab[r0 * ROWU + ks * 8 + tg];
                        a[mt][1] = Ab[(r0 + 8) * ROWU + ks * 8 + tg];
                        a[mt][2] = Ab[r0 * ROWU + ks * 8 + tg + 4];
                        a[mt][3] = Ab[(r0 + 8) * ROWU + ks * 8 + tg + 4];
                    }
                    #pragma unroll
                    for (int nt = 0; nt < 4; nt++) {
                        int nn = noff + nt * 8 + g;
                        b[nt][0] = Bb[nn * ROWU + ks * 8 + tg];
                        b[nt][1] = Bb[nn * ROWU + ks * 8 + tg + 4];
                    }
                    #pragma unroll
                    for (int mt = 0; mt < 4; mt++)
                        #pragma unroll
                        for (int nt = 0; nt < 4; nt++)
                            MMA_F16(acc[mt][nt], a[mt], b[nt]);
                }
            }

            // --- fused epilogue ---
            const int uu = tid & 31;
            const int u  = u0 + uu;
            const float bi = bias[u], bf = bias[UD + u];
            const float bg = bias[2 * UD + u], bo = bias[3 * UD + u];
            float w0i = 0.f, w0f = 0.f, w0g = 0.f, w0o = 0.f;
            if (layer == 0) {
                w0i = W0row[u]; w0f = W0row[UD + u];
                w0g = W0row[2 * UD + u]; w0o = W0row[3 * UD + u];
            }
            float* zsm = (float*)smembuf;   // 64 x 130 floats

            for (int half = 0; half < 2; half++) {
                __syncthreads();
                if (wm == half) {
                    #pragma unroll
                    for (int mt = 0; mt < 4; mt++) {
                        #pragma unroll
                        for (int nt = 0; nt < 4; nt++) {
                            int rl = mt * 16 + g;
                            int cb = noff + nt * 8 + 2 * tg;
                            zsm[rl * 130 + cb]           = acc[mt][nt][0];
                            zsm[rl * 130 + cb + 1]       = acc[mt][nt][1];
                            zsm[(rl + 8) * 130 + cb]     = acc[mt][nt][2];
                            zsm[(rl + 8) * 130 + cb + 1] = acc[mt][nt][3];
                        }
                    }
                }
                __syncthreads();

                #pragma unroll
                for (int r = 0; r < 8; r++) {
                    int ml = wid + r * 8;
                    int brow = m0 + half * 64 + ml;
                    float zi = zsm[ml * 130 + uu]      + bi;
                    float zf = zsm[ml * 130 + 32 + uu] + bf;
                    float zg = zsm[ml * 130 + 64 + uu] + bg;
                    float zo = zsm[ml * 130 + 96 + uu] + bo;
                    if (layer == 0) {
                        float xv = x[(size_t)brow * TT + t];
                        zi += xv * w0i; zf += xv * w0f; zg += xv * w0g; zo += xv * w0o;
                    }
                    float ii = sigf(zi);
                    float ff = sigf(zf);
                    float gg = tanhf(zg);
                    float oo = sigf(zo);

                    size_t idx = (size_t)brow * UD + u;
                    float co = cbuf[idx];
                    float cn = ff * co + ii * gg;
                    float hn = oo * tanhf(cn);

                    size_t midx = (size_t)brow * TT + t;
                    bool msk = mask4 ? (((const unsigned int*)mask)[midx] != 0u)
                                     : (((const unsigned char*)mask)[midx] != 0);
                    if (msk) {
                        cbuf[idx] = cn;
                        hout[idx] = __float2half(hn);
                    } else {
                        hout[idx] = hprev[idx];
                    }
                }
            }
        }

        // ---- grid-wide barrier (epoch s, monotonic counter) ----
        if (tid == 0) {
            __threadfence();
            unsigned arrived = atomicAdd(&g_barcnt, 1u) + 1u;
            unsigned target = (unsigned)nb * (unsigned)(s + 1);
            if (arrived == target) {
                atomicExch(&g_go, (unsigned)(s + 1));
            } else {
                volatile unsigned* vs = &g_go;
                while (*vs < (unsigned)(s + 1)) { __nanosleep(64); }
            }
            __threadfence();
        }
        __syncthreads();
    }
}

// ---------------- head: logits + softmax ----------------
__global__ void k_head(const float* __restrict__ Wd, const float* __restrict__ bd,
                       float* __restrict__ out) {
    __shared__ float wds[UD * NCLS];
    __shared__ float bds[NCLS];
    int tid = threadIdx.x;
    for (int i = tid; i < UD * NCLS; i += 256) wds[i] = Wd[i];
    if (tid < NCLS) bds[tid] = bd[tid];
    __syncthreads();

    int wid = tid >> 5, lane = tid & 31;
    int b = blockIdx.x * 8 + wid;
    const __half* h = g_h16[2][(TT - 1) & 1];

    float p[NCLS];
    #pragma unroll
    for (int c = 0; c < NCLS; c++) p[c] = 0.f;
    for (int k = lane; k < UD; k += 32) {
        float hv = __half2float(h[(size_t)b * UD + k]);
        #pragma unroll
        for (int c = 0; c < NCLS; c++) p[c] += hv * wds[k * NCLS + c];
    }
    #pragma unroll
    for (int off = 16; off; off >>= 1)
        #pragma unroll
        for (int c = 0; c < NCLS; c++)
            p[c] += __shfl_down_sync(0xffffffffu, p[c], off);

    if (lane == 0) {
        float l[NCLS], mx = -1e30f;
        #pragma unroll
        for (int c = 0; c < NCLS; c++) { l[c] = p[c] + bds[c]; mx = fmaxf(mx, l[c]); }
        float ssum = 0.f;
        #pragma unroll
        for (int c = 0; c < NCLS; c++) { l[c] = expf(l[c] - mx); ssum += l[c]; }
        float inv = 1.0f / ssum;
        #pragma unroll
        for (int c = 0; c < NCLS; c++) out[(size_t)b * NCLS + c] = l[c] * inv;
    }
}

// ---------------- launch ----------------
extern "C" void kernel_launch(void* const* d_in, const int* in_sizes, int n_in,
                              void* d_out, int out_size) {
    const float* x    = (const float*)d_in[0];
    const void*  mask = d_in[1];
    const float* W0   = (const float*)d_in[2];
    const float* U0   = (const float*)d_in[3];
    const float* b0   = (const float*)d_in[4];
    const float* W1   = (const float*)d_in[5];
    const float* U1   = (const float*)d_in[6];
    const float* b1   = (const float*)d_in[7];
    const float* W2   = (const float*)d_in[8];
    const float* U2   = (const float*)d_in[9];
    const float* b2   = (const float*)d_in[10];
    const float* Wd   = (const float*)d_in[11];
    const float* bd   = (const float*)d_in[12];
    float* out = (float*)d_out;

    cudaFuncSetAttribute(lstm_persist, cudaFuncAttributeMaxDynamicSharedMemorySize, SMEM_DYN);

    int dev = 0;
    cudaGetDevice(&dev);
    int nsm = 148;
    cudaDeviceGetAttribute(&nsm, cudaDevAttrMultiProcessorCount, dev);
    int perSM = 0;
    cudaOccupancyMaxActiveBlocksPerMultiprocessor(&perSM, lstm_persist, 256, SMEM_DYN);
    if (perSM < 1) perSM = 1;
    int nb = nsm * perSM;
    if (nb > NJOBS) nb = NJOBS;

    k_detect<<<1, 256>>>((const unsigned char*)mask);
    k_zero<<<1024, 256>>>();
    k_trans<<<dim3(G4 / 32, UD / 32, 5), dim3(32, 8)>>>(U0, U1, U2, W1, W2);

    lstm_persist<<<nb, 256, SMEM_DYN>>>(x, mask, W0, b0, b1, b2, nb);

    k_head<<<BATCH / 8, 256>>>(Wd, bd, out);
}

// round 16
// speedup vs baseline: 2.5827x; 1.1104x over previous
#include <cuda_runtime.h>
#include <cuda_fp16.h>
#include <cstdint>

// Problem constants
#define BATCH 2048
#define TT    100
#define UD    512
#define G4    2048      // 4*UD
#define NCLS  10

// Tile constants
#define BM 128
#define NJOBS 768       // 3 layers * 16 mtiles * 16 utiles

// smem: 4-stage pipeline; per stage A=128*80B=10240, B=128*80B=10240
// BK=32 (two m16n8k16 k-steps per stage)
#define ROWB   80       // bytes per smem row (32 halfs data + 8 pad halfs)
#define STAGE_BYTES 20480
#define SMEM_DYN (4 * STAGE_BYTES)   // 81920; z-buffer (64*130*4=33280) fits

// ---------------- scratch (device globals; no allocation) ----------------
__device__ __half g_h16[3][2][BATCH * UD];  // [layer][t&1][b*UD+u]
__device__ float  g_c[3][BATCH * UD];
__device__ __half g_U16[3][G4 * UD];        // transposed: [n][k], k contiguous
__device__ __half g_W16[2][G4 * UD];        // transposed W for layers 1,2
__device__ int    g_mask4;
__device__ unsigned g_ctr[TT + 4];          // per-step job counters
__device__ unsigned g_barcnt;               // monotonic arrival counter
__device__ unsigned g_go;                   // epoch release flag

__device__ __forceinline__ float sigf(float x) {
    return 1.0f / (1.0f + expf(-x));
}

#define CP16(dst, src) \
    asm volatile("cp.async.cg.shared.global [%0], [%1], 16;\n" :: "r"(dst), "l"(src))

#define MMA_F16(d, a, b) \
    asm volatile("mma.sync.aligned.m16n8k16.row.col.f32.f16.f16.f32 " \
        "{%0,%1,%2,%3},{%4,%5,%6,%7},{%8,%9},{%0,%1,%2,%3};\n" \
        : "+f"(d[0]), "+f"(d[1]), "+f"(d[2]), "+f"(d[3]) \
        : "r"(a[0]), "r"(a[1]), "r"(a[2]), "r"(a[3]), "r"(b[0]), "r"(b[1]))

#define LDSM_X4(r0, r1, r2, r3, addr) \
    asm volatile("ldmatrix.sync.aligned.m8n8.x4.shared.b16 {%0,%1,%2,%3}, [%4];\n" \
        : "=r"(r0), "=r"(r1), "=r"(r2), "=r"(r3) : "r"(addr))

// ---------------- mask dtype detection ----------------
__global__ void k_detect(const unsigned char* __restrict__ mask) {
    __shared__ int found;
    if (threadIdx.x == 0) found = 0;
    __syncthreads();
    for (int i = threadIdx.x * 4 + 1; i < 4096; i += blockDim.x * 4)
        if (mask[i]) found = 1;
    __syncthreads();
    if (threadIdx.x == 0) g_mask4 = found ? 0 : 1;
}

// ---------------- zero states + sync vars ----------------
__global__ void k_zero() {
    if (blockIdx.x == 0) {
        if (threadIdx.x == 0) { g_barcnt = 0u; g_go = 0u; }
        if (threadIdx.x < TT + 4) g_ctr[threadIdx.x] = 0u;
    }
    const uint4 z4 = make_uint4(0u, 0u, 0u, 0u);
    size_t nh = (size_t)3 * 2 * BATCH * UD * 2 / 16;   // bytes/16
    uint4* ph = (uint4*)&g_h16[0][0][0];
    for (size_t i = (size_t)blockIdx.x * blockDim.x + threadIdx.x; i < nh;
         i += (size_t)gridDim.x * blockDim.x)
        ph[i] = z4;
    size_t nc = (size_t)3 * BATCH * UD * 4 / 16;
    uint4* pc = (uint4*)&g_c[0][0];
    for (size_t i = (size_t)blockIdx.x * blockDim.x + threadIdx.x; i < nc;
         i += (size_t)gridDim.x * blockDim.x)
        pc[i] = z4;
}

// ---------------- transpose + fp16 convert weights (once) ----------------
__global__ void k_trans(const float* __restrict__ U0, const float* __restrict__ U1,
                        const float* __restrict__ U2, const float* __restrict__ W1,
                        const float* __restrict__ W2) {
    const float* src;
    __half* dst;
    switch (blockIdx.z) {
        case 0: src = U0; dst = g_U16[0]; break;
        case 1: src = U1; dst = g_U16[1]; break;
        case 2: src = U2; dst = g_U16[2]; break;
        case 3: src = W1; dst = g_W16[0]; break;
        default: src = W2; dst = g_W16[1]; break;
    }
    __shared__ float t[32][33];
    int n0 = blockIdx.x * 32, k0 = blockIdx.y * 32;
    int tx = threadIdx.x, ty = threadIdx.y;
    #pragma unroll
    for (int i = 0; i < 4; i++)
        t[ty + i * 8][tx] = src[(size_t)(k0 + ty + i * 8) * G4 + n0 + tx];
    __syncthreads();
    #pragma unroll
    for (int i = 0; i < 4; i++)
        dst[(size_t)(n0 + ty + i * 8) * UD + k0 + tx] = __float2half(t[tx][ty + i * 8]);
}

// ---------------- persistent LSTM: work-stealing + grid barrier ----------------
__global__ __launch_bounds__(256, 2) void lstm_persist(
    const float* __restrict__ x,      // (B, T)
    const void* __restrict__ mask,    // (B, T), 1B or 4B elements
    const float* __restrict__ W0row,  // (2048) layer-0 input weights
    const float* __restrict__ b0,
    const float* __restrict__ b1,
    const float* __restrict__ b2,
    int nb)
{
    extern __shared__ __align__(16) char smembuf[];
    __shared__ int smem_job;
    const uint32_t smemB = (uint32_t)__cvta_generic_to_shared(smembuf);

    const int tid = threadIdx.x;
    const int lane = tid & 31, wid = tid >> 5;
    const int g  = lane >> 2, tg = lane & 3;
    const int wm = wid & 1, wn = wid >> 1;
    const int moff = wm * 64, noff = wn * 32;
    const int mask4 = g_mask4;

    // ---- precomputed ldmatrix per-lane offsets (loop-invariant) ----
    // lane decomposition for m8n8.x4: li = row within matrix, mi = matrix index
    const int li = lane & 7, mi = lane >> 3;
    // A tile mt: matrices [r0..r0+7,k0-7],[r0+8..15,k0-7],[r0..r0+7,k8-15],[r0+8..15,k8-15]
    uint32_t aoff[4];
    #pragma unroll
    for (int mt = 0; mt < 4; mt++)
        aoff[mt] = (uint32_t)((moff + mt * 16 + (mi & 1) * 8 + li) * ROWB + (mi >> 1) * 16);
    // B pair p (covers nt=2p, 2p+1): matrices [n0..7,k0-7],[n0..7,k8-15],[n8..15,k0-7],[n8..15,k8-15]
    // reg order -> b[2p][0], b[2p][1], b[2p+1][0], b[2p+1][1]
    uint32_t boff[2];
    #pragma unroll
    for (int p = 0; p < 2; p++)
        boff[p] = (uint32_t)(10240 + (noff + (p * 2 + (mi >> 1)) * 8 + li) * ROWB + (mi & 1) * 16);

    for (int s = 0; s < TT + 2; s++) {
        // ---- work-stealing loop over this step's jobs ----
        while (true) {
            __syncthreads();   // all threads done with previous smem_job / smem
            if (tid == 0) smem_job = (int)atomicAdd(&g_ctr[s], 1u);
            __syncthreads();
            const int j = smem_job;
            if (j >= NJOBS) break;

            const int layer = j >> 8;
            const int rem = j & 255;
            const int t = s - layer;
            if (t < 0 || t >= TT) continue;

            const int m0 = (rem & 15) * BM;
            const int u0 = (rem >> 4) * 32;

            const __half* hprev = g_h16[layer][(t + 1) & 1];
            __half*       hout  = g_h16[layer][t & 1];
            float*        cbuf  = g_c[layer];
            const __half* in0   = (layer == 0) ? (const __half*)nullptr : g_h16[layer - 1][t & 1];
            const __half* Wsrc  = (layer == 0) ? (const __half*)nullptr : g_W16[layer - 1];
            const __half* Usrc  = g_U16[layer];
            const float*  bias  = (layer == 0) ? b0 : ((layer == 1) ? b1 : b2);
            const int KT = (layer == 0) ? 16 : 32;   // BK=32 per stage

            auto issue = [&](int kt) {
                const __half* As; const __half* Bs; int kk;
                if (layer > 0 && kt < 16) { As = in0;   Bs = Wsrc; kk = kt << 5; }
                else                      { As = hprev; Bs = Usrc; kk = (kt - ((layer > 0) ? 16 : 0)) << 5; }
                const int st = kt & 3;
                uint32_t aB = smemB + st * STAGE_BYTES;
                uint32_t bB = aB + 10240;
                #pragma unroll
                for (int it = 0; it < 2; it++) {
                    int i = tid + it * 256;
                    int m = i >> 2, c = i & 3;
                    const __half* src = As + (size_t)(m0 + m) * UD + kk + c * 8;
                    CP16(aB + (uint32_t)(m * ROWB + c * 16), src);
                }
                #pragma unroll
                for (int it = 0; it < 2; it++) {
                    int i = tid + it * 256;
                    int nl = i >> 2, c = i & 3;
                    int band = nl >> 5, q = nl & 31;
                    int n = band * UD + u0 + q;
                    const __half* src = Bs + (size_t)n * UD + kk + c * 8;
                    CP16(bB + (uint32_t)(nl * ROWB + c * 16), src);
                }
                asm volatile("cp.async.commit_group;\n" ::);
            };

            float acc[4][4][4];
            #pragma unroll
            for (int i = 0; i < 4; i++)
                #pragma unroll
                for (int jj = 0; jj < 4; jj++)
                    #pragma unroll
                    for (int q = 0; q < 4; q++) acc[i][jj][q] = 0.f;

            issue(0);
            issue(1);
            issue(2);

            for (int kt = 0; kt < KT; kt++) {
                int ahead = KT - 1 - kt;     // stages issued beyond kt
                if (ahead >= 2)      { asm volatile("cp.async.wait_group 2;\n" ::); }
                else if (ahead == 1) { asm volatile("cp.async.wait_group 1;\n" ::); }
                else                 { asm volatile("cp.async.wait_group 0;\n" ::); }
                __syncthreads();
                if (kt + 3 < KT) issue(kt + 3);

                const uint32_t stBase = smemB + (uint32_t)(kt & 3) * STAGE_BYTES;

                #pragma unroll
                for (int ks = 0; ks < 2; ks++) {
                    const uint32_t ko = (uint32_t)(ks * 32);
                    uint32_t a[4][4], bq[2][4];
                    #pragma unroll
                    for (int mt = 0; mt < 4; mt++)
                        LDSM_X4(a[mt][0], a[mt][1], a[mt][2], a[mt][3],
                                stBase + aoff[mt] + ko);
                    #pragma unroll
                    for (int p = 0; p < 2; p++)
                        LDSM_X4(bq[p][0], bq[p][1], bq[p][2], bq[p][3],
                                stBase + boff[p] + ko);
                    #pragma unroll
                    for (int mt = 0; mt < 4; mt++)
                        #pragma unroll
                        for (int nt = 0; nt < 4; nt++)
                            MMA_F16(acc[mt][nt], a[mt], (&bq[nt >> 1][(nt & 1) * 2]));
                }
            }

            // --- fused epilogue ---
            const int uu = tid & 31;
            const int u  = u0 + uu;
            const float bi = bias[u], bf = bias[UD + u];
            const float bg = bias[2 * UD + u], bo = bias[3 * UD + u];
            float w0i = 0.f, w0f = 0.f, w0g = 0.f, w0o = 0.f;
            if (layer == 0) {
                w0i = W0row[u]; w0f = W0row[UD + u];
                w0g = W0row[2 * UD + u]; w0o = W0row[3 * UD + u];
            }
            float* zsm = (float*)smembuf;   // 64 x 130 floats

            for (int half = 0; half < 2; half++) {
                __syncthreads();
                if (wm == half) {
                    #pragma unroll
                    for (int mt = 0; mt < 4; mt++) {
                        #pragma unroll
                        for (int nt = 0; nt < 4; nt++) {
                            int rl = mt * 16 + g;
                            int cb = noff + nt * 8 + 2 * tg;
                            zsm[rl * 130 + cb]           = acc[mt][nt][0];
                            zsm[rl * 130 + cb + 1]       = acc[mt][nt][1];
                            zsm[(rl + 8) * 130 + cb]     = acc[mt][nt][2];
                            zsm[(rl + 8) * 130 + cb + 1] = acc[mt][nt][3];
                        }
                    }
                }
                __syncthreads();

                #pragma unroll
                for (int r = 0; r < 8; r++) {
                    int ml = wid + r * 8;
                    int brow = m0 + half * 64 + ml;
                    float zi = zsm[ml * 130 + uu]      + bi;
                    float zf = zsm[ml * 130 + 32 + uu] + bf;
                    float zg = zsm[ml * 130 + 64 + uu] + bg;
                    float zo = zsm[ml * 130 + 96 + uu] + bo;
                    if (layer == 0) {
                        float xv = x[(size_t)brow * TT + t];
                        zi += xv * w0i; zf += xv * w0f; zg += xv * w0g; zo += xv * w0o;
                    }
                    float ii = sigf(zi);
                    float ff = sigf(zf);
                    float gg = tanhf(zg);
                    float oo = sigf(zo);

                    size_t idx = (size_t)brow * UD + u;
                    float co = cbuf[idx];
                    float cn = ff * co + ii * gg;
                    float hn = oo * tanhf(cn);

                    size_t midx = (size_t)brow * TT + t;
                    bool msk = mask4 ? (((const unsigned int*)mask)[midx] != 0u)
                                     : (((const unsigned char*)mask)[midx] != 0);
                    if (msk) {
                        cbuf[idx] = cn;
                        hout[idx] = __float2half(hn);
                    } else {
                        hout[idx] = hprev[idx];
                    }
                }
            }
        }

        // ---- grid-wide barrier (epoch s, monotonic counter) ----
        if (tid == 0) {
            __threadfence();
            unsigned arrived = atomicAdd(&g_barcnt, 1u) + 1u;
            unsigned target = (unsigned)nb * (unsigned)(s + 1);
            if (arrived == target) {
                atomicExch(&g_go, (unsigned)(s + 1));
            } else {
                volatile unsigned* vs = &g_go;
                while (*vs < (unsigned)(s + 1)) { __nanosleep(64); }
            }
            __threadfence();
        }
        __syncthreads();
    }
}

// ---------------- head: logits + softmax ----------------
__global__ void k_head(const float* __restrict__ Wd, const float* __restrict__ bd,
                       float* __restrict__ out) {
    __shared__ float wds[UD * NCLS];
    __shared__ float bds[NCLS];
    int tid = threadIdx.x;
    for (int i = tid; i < UD * NCLS; i += 256) wds[i] = Wd[i];
    if (tid < NCLS) bds[tid] = bd[tid];
    __syncthreads();

    int wid = tid >> 5, lane = tid & 31;
    int b = blockIdx.x * 8 + wid;
    const __half* h = g_h16[2][(TT - 1) & 1];

    float p[NCLS];
    #pragma unroll
    for (int c = 0; c < NCLS; c++) p[c] = 0.f;
    for (int k = lane; k < UD; k += 32) {
        float hv = __half2float(h[(size_t)b * UD + k]);
        #pragma unroll
        for (int c = 0; c < NCLS; c++) p[c] += hv * wds[k * NCLS + c];
    }
    #pragma unroll
    for (int off = 16; off; off >>= 1)
        #pragma unroll
        for (int c = 0; c < NCLS; c++)
            p[c] += __shfl_down_sync(0xffffffffu, p[c], off);

    if (lane == 0) {
        float l[NCLS], mx = -1e30f;
        #pragma unroll
        for (int c = 0; c < NCLS; c++) { l[c] = p[c] + bds[c]; mx = fmaxf(mx, l[c]); }
        float ssum = 0.f;
        #pragma unroll
        for (int c = 0; c < NCLS; c++) { l[c] = expf(l[c] - mx); ssum += l[c]; }
        float inv = 1.0f / ssum;
        #pragma unroll
        for (int c = 0; c < NCLS; c++) out[(size_t)b * NCLS + c] = l[c] * inv;
    }
}

// ---------------- launch ----------------
extern "C" void kernel_launch(void* const* d_in, const int* in_sizes, int n_in,
                              void* d_out, int out_size) {
    const float* x    = (const float*)d_in[0];
    const void*  mask = d_in[1];
    const float* W0   = (const float*)d_in[2];
    const float* U0   = (const float*)d_in[3];
    const float* b0   = (const float*)d_in[4];
    const float* W1   = (const float*)d_in[5];
    const float* U1   = (const float*)d_in[6];
    const float* b1   = (const float*)d_in[7];
    const float* W2   = (const float*)d_in[8];
    const float* U2   = (const float*)d_in[9];
    const float* b2   = (const float*)d_in[10];
    const float* Wd   = (const float*)d_in[11];
    const float* bd   = (const float*)d_in[12];
    float* out = (float*)d_out;

    cudaFuncSetAttribute(lstm_persist, cudaFuncAttributeMaxDynamicSharedMemorySize, SMEM_DYN);

    int dev = 0;
    cudaGetDevice(&dev);
    int nsm = 148;
    cudaDeviceGetAttribute(&nsm, cudaDevAttrMultiProcessorCount, dev);
    int perSM = 0;
    cudaOccupancyMaxActiveBlocksPerMultiprocessor(&perSM, lstm_persist, 256, SMEM_DYN);
    if (perSM < 1) perSM = 1;
    int nb = nsm * perSM;
    if (nb > NJOBS) nb = NJOBS;

    k_detect<<<1, 256>>>((const unsigned char*)mask);
    k_zero<<<1024, 256>>>();
    k_trans<<<dim3(G4 / 32, UD / 32, 5), dim3(32, 8)>>>(U0, U1, U2, W1, W2);

    lstm_persist<<<nb, 256, SMEM_DYN>>>(x, mask, W0, b0, b1, b2, nb);

    k_head<<<BATCH / 8, 256>>>(Wd, bd, out);
}